// round 2
// baseline (speedup 1.0000x reference)
#include <cuda_runtime.h>
#include <math.h>

#define B_ 64
#define F_ 256
#define T_ 1024
#define H_ 1024
#define O_ 512

#define NB   128            // persistent blocks (<= 148 SMs -> all co-resident)
#define NKS  4              // k-splits
#define KSL  (H_ / NKS)     // 256 k per block
#define HT   32             // h columns per block
#define KC   32             // k chunk staged in smem

// Scratch: buf[t][b][h]. xb before step t, state s_t after (in-place).
__device__ float g_buf[(size_t)T_ * B_ * H_];          // 256 MB
__device__ float g_part[NKS * B_ * H_];                // 1 MB partials
__device__ unsigned g_cnt = 0;                         // barrier arrivals
__device__ unsigned g_rel = 0;                         // barrier release (monotonic)

// ---------------------------------------------------------------------------
// Grid barrier: monotonic release counter, base-relative targets -> safe
// across graph replays. __threadfence() (gpu scope) emits CCTL.IVALL on
// sm_103a, invalidating this SM's L1D so post-barrier loads see fresh data.
// ---------------------------------------------------------------------------
__device__ __forceinline__ void gsync(unsigned target) {
    __syncthreads();
    if (threadIdx.x == 0) {
        __threadfence();
        unsigned old = atomicAdd(&g_cnt, 1u);
        if (old == NB - 1) {
            g_cnt = 0;
            __threadfence();
            atomicExch(&g_rel, target);
        } else {
            while ((int)(*(volatile unsigned*)&g_rel - target) < 0) {
                __nanosleep(32);
            }
        }
        __threadfence();
    }
    __syncthreads();
}

// ---------------------------------------------------------------------------
// Kernel 1: buf[t][b][h] = bias[h] + sum_f x[b][f][t] * Wx[f][h]
// ---------------------------------------------------------------------------
__global__ __launch_bounds__(256) void k_xw(const float* __restrict__ x,
                                            const float* __restrict__ Wx,
                                            const float* __restrict__ bias) {
    const int BM = 128, BN = 128, BK = 8;
    __shared__ float As[BK][BM];
    __shared__ float Bs[BK][BN];

    int tid = threadIdx.x;
    int tx = tid % 16, ty = tid / 16;
    int n0 = blockIdx.x * BN;
    int mtile = blockIdx.y;
    int b  = mtile / (T_ / BM);
    int t0 = (mtile % (T_ / BM)) * BM;

    float acc[8][8];
#pragma unroll
    for (int i = 0; i < 8; i++)
#pragma unroll
        for (int j = 0; j < 8; j++) acc[i][j] = 0.f;

    const float* xb = x + (size_t)b * F_ * T_ + t0;

    for (int kc = 0; kc < F_; kc += BK) {
#pragma unroll
        for (int i = 0; i < 4; i++) {
            int e = i * 256 + tid;
            int mm = e % BM, kk = e / BM;
            As[kk][mm] = xb[(size_t)(kc + kk) * T_ + mm];
        }
#pragma unroll
        for (int i = 0; i < 4; i++) {
            int e = i * 256 + tid;
            int nn = e % BN, kk = e / BN;
            Bs[kk][nn] = Wx[(size_t)(kc + kk) * H_ + n0 + nn];
        }
        __syncthreads();
#pragma unroll
        for (int k = 0; k < BK; k++) {
            float ra[8], rb[8];
#pragma unroll
            for (int i = 0; i < 8; i++) ra[i] = As[k][ty + 16 * i];
#pragma unroll
            for (int j = 0; j < 8; j++) rb[j] = Bs[k][tx + 16 * j];
#pragma unroll
            for (int i = 0; i < 8; i++)
#pragma unroll
                for (int j = 0; j < 8; j++) acc[i][j] += ra[i] * rb[j];
        }
        __syncthreads();
    }

#pragma unroll
    for (int i = 0; i < 8; i++) {
        int t = t0 + ty + 16 * i;
        float* dst = g_buf + ((size_t)t * B_ + b) * H_ + n0;
#pragma unroll
        for (int j = 0; j < 8; j++) {
            int n = tx + 16 * j;
            dst[n] = acc[i][j] + bias[n0 + n];
        }
    }
}

// ---------------------------------------------------------------------------
// Kernel 2: persistent recurrence. One launch, 2T-1 grid barriers.
// Block (ks, ht): partial C[64 b][32 h] over k in [ks*256, ks*256+256).
// Wh slice (256x32 = 32KB) cached in smem for ALL steps.
// 128 threads, 4x4 register tile (bg = tid&15 -> 4 b rows, hg = tid>>4 -> 4 h).
// ---------------------------------------------------------------------------
__global__ __launch_bounds__(128, 1) void k_rnn(const float* __restrict__ Wh) {
    __shared__ float sW[KSL][HT];       // 32 KB, persistent
    __shared__ float sS[KC][68];        // staged s chunk [k][b], padded row

    const int tid = threadIdx.x;
    const int bx  = blockIdx.x;
    const int ks  = bx >> 5;            // 0..3
    const int ht  = bx & 31;            // 0..31
    const int k0  = ks * KSL;
    const int h0  = ht * HT;
    const int bg  = tid & 15;           // b quad
    const int hg  = tid >> 4;           // h quad

    // Load Wh slice once
    for (int i = tid; i < KSL * HT; i += 128) {
        int kk = i >> 5, hh = i & 31;
        sW[kk][hh] = Wh[(size_t)(k0 + kk) * H_ + h0 + hh];
    }
    __syncthreads();

    unsigned base = *(volatile unsigned*)&g_rel;
    unsigned bar = 0;

    const int pb_idx = bx * 128 + tid;  // 0..16383, one float4 of [b][h] each

    for (int t = 0; t < T_; ++t) {
        // ---- Phase A: partial GEMM over s_{t-1} ----
        if (t > 0) {
            const float* sp = g_buf + (size_t)(t - 1) * B_ * H_;
            float acc[4][4];
#pragma unroll
            for (int i = 0; i < 4; i++)
#pragma unroll
                for (int j = 0; j < 4; j++) acc[i][j] = 0.f;

            // software-pipelined chunk loads: regs -> smem -> compute
            float4 pv[4];
#pragma unroll
            for (int it = 0; it < 4; it++) {
                int idx = it * 128 + tid;
                int kk = idx & 31, bq = idx >> 5;
                const float* s0 = sp + k0 + kk;
                pv[it].x = s0[(size_t)(bq * 4 + 0) * H_];
                pv[it].y = s0[(size_t)(bq * 4 + 1) * H_];
                pv[it].z = s0[(size_t)(bq * 4 + 2) * H_];
                pv[it].w = s0[(size_t)(bq * 4 + 3) * H_];
            }

            for (int c = 0; c < KSL / KC; ++c) {
                __syncthreads();  // prior chunk's compute done
#pragma unroll
                for (int it = 0; it < 4; it++) {
                    int idx = it * 128 + tid;
                    int kk = idx & 31, bq = idx >> 5;
                    *reinterpret_cast<float4*>(&sS[kk][bq * 4]) = pv[it];
                }
                __syncthreads();
                if (c + 1 < KSL / KC) {
#pragma unroll
                    for (int it = 0; it < 4; it++) {
                        int idx = it * 128 + tid;
                        int kk = idx & 31, bq = idx >> 5;
                        const float* s0 = sp + k0 + (c + 1) * KC + kk;
                        pv[it].x = s0[(size_t)(bq * 4 + 0) * H_];
                        pv[it].y = s0[(size_t)(bq * 4 + 1) * H_];
                        pv[it].z = s0[(size_t)(bq * 4 + 2) * H_];
                        pv[it].w = s0[(size_t)(bq * 4 + 3) * H_];
                    }
                }
#pragma unroll
                for (int k = 0; k < KC; k++) {
                    float4 sv = *reinterpret_cast<const float4*>(&sS[k][bg * 4]);
                    float4 wv = *reinterpret_cast<const float4*>(&sW[c * KC + k][hg * 4]);
                    acc[0][0] += sv.x * wv.x; acc[0][1] += sv.x * wv.y;
                    acc[0][2] += sv.x * wv.z; acc[0][3] += sv.x * wv.w;
                    acc[1][0] += sv.y * wv.x; acc[1][1] += sv.y * wv.y;
                    acc[1][2] += sv.y * wv.z; acc[1][3] += sv.y * wv.w;
                    acc[2][0] += sv.z * wv.x; acc[2][1] += sv.z * wv.y;
                    acc[2][2] += sv.z * wv.z; acc[2][3] += sv.z * wv.w;
                    acc[3][0] += sv.w * wv.x; acc[3][1] += sv.w * wv.y;
                    acc[3][2] += sv.w * wv.z; acc[3][3] += sv.w * wv.w;
                }
            }

            // write partials
#pragma unroll
            for (int i = 0; i < 4; i++) {
                float4 r = make_float4(acc[i][0], acc[i][1], acc[i][2], acc[i][3]);
                *reinterpret_cast<float4*>(
                    &g_part[(size_t)ks * B_ * H_ + (size_t)(bg * 4 + i) * H_ + h0 + hg * 4]) = r;
            }
            gsync(base + (++bar));
        }

        // ---- Phase B: s_t = tanh(xb + sum_ks partial) in place ----
        {
            float4* cur = reinterpret_cast<float4*>(g_buf + (size_t)t * B_ * H_);
            float4 v = cur[pb_idx];
            if (t > 0) {
#pragma unroll
                for (int p = 0; p < NKS; p++) {
                    float4 pp = reinterpret_cast<const float4*>(g_part + (size_t)p * B_ * H_)[pb_idx];
                    v.x += pp.x; v.y += pp.y; v.z += pp.z; v.w += pp.w;
                }
            }
            v.x = tanhf(v.x); v.y = tanhf(v.y);
            v.z = tanhf(v.z); v.w = tanhf(v.w);
            cur[pb_idx] = v;
        }
        gsync(base + (++bar));
    }
}

// ---------------------------------------------------------------------------
// Kernel 3: out[b][t][o] = bout[o] + sum_h buf[t][b][h] * Wout[h][o]
// ---------------------------------------------------------------------------
__global__ __launch_bounds__(256) void k_out(const float* __restrict__ Wout,
                                             const float* __restrict__ bout,
                                             float* __restrict__ out) {
    const int BM = 128, BN = 128, BK = 8;
    __shared__ float As[BK][BM + 4];
    __shared__ float Bs[BK][BN];

    int tid = threadIdx.x;
    int tx = tid % 16, ty = tid / 16;
    int n0 = blockIdx.x * BN;
    int m0 = blockIdx.y * BM;

    float acc[8][8];
#pragma unroll
    for (int i = 0; i < 8; i++)
#pragma unroll
        for (int j = 0; j < 8; j++) acc[i][j] = 0.f;

    const float* A = g_buf;  // [m][k], m = t*B + b, K = H_

    for (int kc = 0; kc < H_; kc += BK) {
        {
            int mm = tid >> 1;
            int kq = (tid & 1) * 4;
            float4 v = *reinterpret_cast<const float4*>(
                &A[(size_t)(m0 + mm) * H_ + kc + kq]);
            As[kq + 0][mm] = v.x;
            As[kq + 1][mm] = v.y;
            As[kq + 2][mm] = v.z;
            As[kq + 3][mm] = v.w;
        }
#pragma unroll
        for (int i = 0; i < 4; i++) {
            int e = i * 256 + tid;
            int nn = e % BN, kk = e / BN;
            Bs[kk][nn] = Wout[(size_t)(kc + kk) * O_ + n0 + nn];
        }
        __syncthreads();
#pragma unroll
        for (int k = 0; k < BK; k++) {
            float ra[8], rb[8];
#pragma unroll
            for (int i = 0; i < 8; i++) ra[i] = As[k][ty + 16 * i];
#pragma unroll
            for (int j = 0; j < 8; j++) rb[j] = Bs[k][tx + 16 * j];
#pragma unroll
            for (int i = 0; i < 8; i++)
#pragma unroll
                for (int j = 0; j < 8; j++) acc[i][j] += ra[i] * rb[j];
        }
        __syncthreads();
    }

#pragma unroll
    for (int i = 0; i < 8; i++) {
        int m = m0 + ty + 16 * i;
        int t = m / B_;
        int b = m % B_;
        float* dst = out + ((size_t)b * T_ + t) * O_ + n0;
#pragma unroll
        for (int j = 0; j < 8; j++) {
            int n = tx + 16 * j;
            dst[n] = acc[i][j] + bout[n0 + n];
        }
    }
}

extern "C" void kernel_launch(void* const* d_in, const int* in_sizes, int n_in,
                              void* d_out, int out_size) {
    const float* x    = (const float*)d_in[0];
    const float* Wx   = (const float*)d_in[1];
    const float* Wh   = (const float*)d_in[2];
    const float* bias = (const float*)d_in[3];
    const float* Wout = (const float*)d_in[4];
    const float* bout = (const float*)d_in[5];
    float* out = (float*)d_out;

    (void)in_sizes; (void)n_in; (void)out_size;

    dim3 g1(H_ / 128, (B_ * T_) / 128);   // (8, 512)
    k_xw<<<g1, 256>>>(x, Wx, bias);

    k_rnn<<<NB, 128>>>(Wh);               // single persistent launch

    dim3 g3(O_ / 128, (B_ * T_) / 128);   // (4, 512)
    k_out<<<g3, 256>>>(Wout, bout, out);
}

// round 4
// speedup vs baseline: 1.0750x; 1.0750x over previous
#include <cuda_runtime.h>
#include <math.h>

#define B_ 64
#define F_ 256
#define T_ 1024
#define H_ 1024
#define O_ 512

#define NB   128          // persistent blocks, one wave (<=148 SMs)
#define BT   16           // b rows per block   (4 b-tiles)
#define HT2  32           // h cols per block   (32 h-tiles)
#define KC   128          // k chunk staged in smem
#define WPAD 4            // sWh row pad (floats)
#define SPAD 4            // sS row pad (floats)

#define WROW (H_ + WPAD)          // 1028
#define SROW (KC + SPAD)          // 132
#define SMEM_RNN ((HT2 * WROW + 2 * BT * SROW) * 4)   // 148480 bytes

// Scratch: buf[t][b][h]. Holds xb before step t, state s_t after (in place).
__device__ float g_buf[(size_t)T_ * B_ * H_];   // 256 MB
__device__ unsigned g_flags[NB];                // barrier arrival flags
__device__ unsigned g_rel2;                     // barrier release (monotonic)

// ---------------------------------------------------------------------------
// Distributed-flag grid barrier. Arrivals are parallel stores to distinct
// addresses (no atomic serialization); block 0's 128 threads scan all flags;
// single release word. Monotonic epochs -> safe across graph replays.
// ---------------------------------------------------------------------------
__device__ __forceinline__ void gsync(unsigned target) {
    __syncthreads();                    // all block stores issued
    if (blockIdx.x == 0) {
        if (threadIdx.x == 0) {
            __threadfence();            // order data before flag (gpu scope)
            *(volatile unsigned*)&g_flags[0] = target;
        }
        unsigned i = threadIdx.x;       // 128 threads scan 128 flags
        while ((int)(*(volatile unsigned*)&g_flags[i] - target) < 0)
            __nanosleep(40);
        __syncthreads();
        if (threadIdx.x == 0) {
            __threadfence();
            *(volatile unsigned*)&g_rel2 = target;
        }
        __syncthreads();
    } else {
        if (threadIdx.x == 0) {
            __threadfence();            // order data before flag (gpu scope)
            *(volatile unsigned*)&g_flags[blockIdx.x] = target;
            while ((int)(*(volatile unsigned*)&g_rel2 - target) < 0)
                __nanosleep(40);
            __threadfence();            // acquire
        }
        __syncthreads();
    }
}

// ---------------------------------------------------------------------------
// Kernel 1: buf[t][b][h] = bias[h] + sum_f x[b][f][t] * Wx[f][h]
// ---------------------------------------------------------------------------
__global__ __launch_bounds__(256) void k_xw(const float* __restrict__ x,
                                            const float* __restrict__ Wx,
                                            const float* __restrict__ bias) {
    const int BM = 128, BN = 128, BK = 8;
    __shared__ float As[BK][BM];
    __shared__ float Bs[BK][BN];

    int tid = threadIdx.x;
    int tx = tid % 16, ty = tid / 16;
    int n0 = blockIdx.x * BN;
    int mtile = blockIdx.y;
    int b  = mtile / (T_ / BM);
    int t0 = (mtile % (T_ / BM)) * BM;

    float acc[8][8];
#pragma unroll
    for (int i = 0; i < 8; i++)
#pragma unroll
        for (int j = 0; j < 8; j++) acc[i][j] = 0.f;

    const float* xb = x + (size_t)b * F_ * T_ + t0;

    for (int kc = 0; kc < F_; kc += BK) {
#pragma unroll
        for (int i = 0; i < 4; i++) {
            int e = i * 256 + tid;
            int mm = e % BM, kk = e / BM;
            As[kk][mm] = xb[(size_t)(kc + kk) * T_ + mm];
        }
#pragma unroll
        for (int i = 0; i < 4; i++) {
            int e = i * 256 + tid;
            int nn = e % BN, kk = e / BN;
            Bs[kk][nn] = Wx[(size_t)(kc + kk) * H_ + n0 + nn];
        }
        __syncthreads();
#pragma unroll
        for (int k = 0; k < BK; k++) {
            float ra[8], rb[8];
#pragma unroll
            for (int i = 0; i < 8; i++) ra[i] = As[k][ty + 16 * i];
#pragma unroll
            for (int j = 0; j < 8; j++) rb[j] = Bs[k][tx + 16 * j];
#pragma unroll
            for (int i = 0; i < 8; i++)
#pragma unroll
                for (int j = 0; j < 8; j++) acc[i][j] += ra[i] * rb[j];
        }
        __syncthreads();
    }

#pragma unroll
    for (int i = 0; i < 8; i++) {
        int t = t0 + ty + 16 * i;
        float* dst = g_buf + ((size_t)t * B_ + b) * H_ + n0;
#pragma unroll
        for (int j = 0; j < 8; j++) {
            int n = tx + 16 * j;
            dst[n] = acc[i][j] + bias[n0 + n];
        }
    }
}

// ---------------------------------------------------------------------------
// Kernel 2: persistent recurrence, ONE grid barrier per step.
// Block (bt, ht): C[16 b][32 h] over full K=1024.
//   s_t[tile] = tanh(xb[tile] + s_{t-1}[b rows] @ Wh[:, h cols])
// Wh slice transposed+resident in smem: sWh[h][k] (128 KB, loaded once).
// 128 threads, thread tile 2b x 2h, float4 vectorization along k.
// ---------------------------------------------------------------------------
__global__ __launch_bounds__(128, 1) void k_rnn(const float* __restrict__ Wh) {
    extern __shared__ float smem[];
    float* sWh = smem;                      // [HT2][WROW]
    float* sS  = smem + HT2 * WROW;         // [2][BT][SROW]

    const int tid = threadIdx.x;
    const int bx  = blockIdx.x;
    const int bt  = bx >> 5;                // 0..3
    const int ht  = bx & 31;                // 0..31
    const int b0  = bt * BT;
    const int h0  = ht * HT2;
    const int hIdx = tid & 15;              // h, h+16
    const int bIdx = tid >> 4;              // b, b+8   (0..7)

    // ---- Load Wh slice once, transposed: sWh[h][k] = Wh[k][h0+h] ----
    for (int i = tid; i < HT2 * H_ / 4; i += 128) {
        int k  = i >> 3;
        int hq = (i & 7) * 4;
        float4 v = *reinterpret_cast<const float4*>(&Wh[(size_t)k * H_ + h0 + hq]);
        sWh[(size_t)(hq + 0) * WROW + k] = v.x;
        sWh[(size_t)(hq + 1) * WROW + k] = v.y;
        sWh[(size_t)(hq + 2) * WROW + k] = v.z;
        sWh[(size_t)(hq + 3) * WROW + k] = v.w;
    }
    __syncthreads();

    const float* sW0 = &sWh[(size_t)hIdx * WROW];
    const float* sW1 = &sWh[(size_t)(hIdx + 16) * WROW];

    unsigned base = *(volatile unsigned*)&g_rel2;
    unsigned bar = 0;

    // epilogue global offsets for this thread's 2x2 tile
    const int gb0 = b0 + bIdx, gb1 = b0 + bIdx + 8;
    const int gh0 = h0 + hIdx, gh1 = h0 + hIdx + 16;

    for (int t = 0; t < T_; ++t) {
        float* cur = g_buf + (size_t)t * B_ * H_;

        // prefetch xb for this thread's outputs (hides L2 latency behind GEMM)
        float xb00 = cur[(size_t)gb0 * H_ + gh0];
        float xb01 = cur[(size_t)gb0 * H_ + gh1];
        float xb10 = cur[(size_t)gb1 * H_ + gh0];
        float xb11 = cur[(size_t)gb1 * H_ + gh1];

        float a00 = 0.f, a01 = 0.f, a10 = 0.f, a11 = 0.f;

        if (t > 0) {
            const float* sp = g_buf + (size_t)(t - 1) * B_ * H_ + (size_t)b0 * H_;

            // preload chunk 0 into registers
            float4 pv[4];
#pragma unroll
            for (int it = 0; it < 4; it++) {
                int idx = it * 128 + tid;
                int row = idx >> 5, q = idx & 31;
                pv[it] = *reinterpret_cast<const float4*>(
                    &sp[(size_t)row * H_ + q * 4]);
            }

            for (int c = 0; c < H_ / KC; ++c) {
                float* sb = sS + (c & 1) * (BT * SROW);
                __syncthreads();   // buffer free (compute from 2 chunks ago done)
#pragma unroll
                for (int it = 0; it < 4; it++) {
                    int idx = it * 128 + tid;
                    int row = idx >> 5, q = idx & 31;
                    *reinterpret_cast<float4*>(&sb[row * SROW + q * 4]) = pv[it];
                }
                __syncthreads();   // chunk c visible
                if (c + 1 < H_ / KC) {
                    const float* spn = sp + (c + 1) * KC;
#pragma unroll
                    for (int it = 0; it < 4; it++) {
                        int idx = it * 128 + tid;
                        int row = idx >> 5, q = idx & 31;
                        pv[it] = *reinterpret_cast<const float4*>(
                            &spn[(size_t)row * H_ + q * 4]);
                    }
                }
                const float* s0r = &sb[bIdx * SROW];
                const float* s1r = &sb[(bIdx + 8) * SROW];
                const float* w0r = sW0 + c * KC;
                const float* w1r = sW1 + c * KC;
#pragma unroll 8
                for (int q = 0; q < KC / 4; q++) {
                    float4 s0 = *reinterpret_cast<const float4*>(&s0r[q * 4]);
                    float4 s1 = *reinterpret_cast<const float4*>(&s1r[q * 4]);
                    float4 w0 = *reinterpret_cast<const float4*>(&w0r[q * 4]);
                    float4 w1 = *reinterpret_cast<const float4*>(&w1r[q * 4]);
                    a00 += s0.x * w0.x; a01 += s0.x * w1.x;
                    a10 += s1.x * w0.x; a11 += s1.x * w1.x;
                    a00 += s0.y * w0.y; a01 += s0.y * w1.y;
                    a10 += s1.y * w0.y; a11 += s1.y * w1.y;
                    a00 += s0.z * w0.z; a01 += s0.z * w1.z;
                    a10 += s1.z * w0.z; a11 += s1.z * w1.z;
                    a00 += s0.w * w0.w; a01 += s0.w * w1.w;
                    a10 += s1.w * w0.w; a11 += s1.w * w1.w;
                }
            }
        }

        // ---- epilogue: s_t = tanh(xb + acc), in place ----
        cur[(size_t)gb0 * H_ + gh0] = tanhf(xb00 + a00);
        cur[(size_t)gb0 * H_ + gh1] = tanhf(xb01 + a01);
        cur[(size_t)gb1 * H_ + gh0] = tanhf(xb10 + a10);
        cur[(size_t)gb1 * H_ + gh1] = tanhf(xb11 + a11);

        gsync(base + (++bar));
    }
}

// ---------------------------------------------------------------------------
// Kernel 3: out[b][t][o] = bout[o] + sum_h buf[t][b][h] * Wout[h][o]
// ---------------------------------------------------------------------------
__global__ __launch_bounds__(256) void k_out(const float* __restrict__ Wout,
                                             const float* __restrict__ bout,
                                             float* __restrict__ out) {
    const int BM = 128, BN = 128, BK = 8;
    __shared__ float As[BK][BM + 4];
    __shared__ float Bs[BK][BN];

    int tid = threadIdx.x;
    int tx = tid % 16, ty = tid / 16;
    int n0 = blockIdx.x * BN;
    int m0 = blockIdx.y * BM;

    float acc[8][8];
#pragma unroll
    for (int i = 0; i < 8; i++)
#pragma unroll
        for (int j = 0; j < 8; j++) acc[i][j] = 0.f;

    const float* A = g_buf;  // [m][k], m = t*B + b, K = H_

    for (int kc = 0; kc < H_; kc += BK) {
        {
            int mm = tid >> 1;
            int kq = (tid & 1) * 4;
            float4 v = *reinterpret_cast<const float4*>(
                &A[(size_t)(m0 + mm) * H_ + kc + kq]);
            As[kq + 0][mm] = v.x;
            As[kq + 1][mm] = v.y;
            As[kq + 2][mm] = v.z;
            As[kq + 3][mm] = v.w;
        }
#pragma unroll
        for (int i = 0; i < 4; i++) {
            int e = i * 256 + tid;
            int nn = e % BN, kk = e / BN;
            Bs[kk][nn] = Wout[(size_t)(kc + kk) * O_ + n0 + nn];
        }
        __syncthreads();
#pragma unroll
        for (int k = 0; k < BK; k++) {
            float ra[8], rb[8];
#pragma unroll
            for (int i = 0; i < 8; i++) ra[i] = As[k][ty + 16 * i];
#pragma unroll
            for (int j = 0; j < 8; j++) rb[j] = Bs[k][tx + 16 * j];
#pragma unroll
            for (int i = 0; i < 8; i++)
#pragma unroll
                for (int j = 0; j < 8; j++) acc[i][j] += ra[i] * rb[j];
        }
        __syncthreads();
    }

#pragma unroll
    for (int i = 0; i < 8; i++) {
        int m = m0 + ty + 16 * i;
        int t = m / B_;
        int b = m % B_;
        float* dst = out + ((size_t)b * T_ + t) * O_ + n0;
#pragma unroll
        for (int j = 0; j < 8; j++) {
            int n = tx + 16 * j;
            dst[n] = acc[i][j] + bout[n0 + n];
        }
    }
}

extern "C" void kernel_launch(void* const* d_in, const int* in_sizes, int n_in,
                              void* d_out, int out_size) {
    const float* x    = (const float*)d_in[0];
    const float* Wx   = (const float*)d_in[1];
    const float* Wh   = (const float*)d_in[2];
    const float* bias = (const float*)d_in[3];
    const float* Wout = (const float*)d_in[4];
    const float* bout = (const float*)d_in[5];
    float* out = (float*)d_out;

    (void)in_sizes; (void)n_in; (void)out_size;

    // opt-in to 148.5 KB dynamic smem for the persistent kernel (idempotent)
    cudaFuncSetAttribute(k_rnn, cudaFuncAttributeMaxDynamicSharedMemorySize,
                         SMEM_RNN);

    dim3 g1(H_ / 128, (B_ * T_) / 128);   // (8, 512)
    k_xw<<<g1, 256>>>(x, Wx, bias);

    k_rnn<<<NB, 128, SMEM_RNN>>>(Wh);     // single persistent launch

    dim3 g3(O_ / 128, (B_ * T_) / 128);   // (4, 512)
    k_out<<<g3, 256>>>(Wout, bout, out);
}